// round 2
// baseline (speedup 1.0000x reference)
#include <cuda_runtime.h>
#include <math.h>

#define B_ 32
#define T_ 128
#define E_ 512
#define H_ 256
#define V_ 32000
#define G_ 1024  // 4*H

// ---------------- scratch (device globals; no allocations) ----------------
__device__ float g_Ucat[E_ * G_];      // [E][4H]   2 MB
__device__ float g_Whcat[H_ * G_];     // [H][4H]   1 MB
__device__ float g_bcat[G_];           // [4H]
__device__ float g_xproj[T_ * B_ * G_]; // [T][B][4H] 16 MB
__device__ float g_hs[T_ * B_ * H_];    // [T][B][H]   4 MB

// ---------------- pack gate weights into concatenated layout ----------------
__global__ void pack_kernel(const float* __restrict__ Ui, const float* __restrict__ Uf,
                            const float* __restrict__ Ug, const float* __restrict__ Uo,
                            const float* __restrict__ Wi, const float* __restrict__ Wf,
                            const float* __restrict__ Wg, const float* __restrict__ Wo,
                            const float* __restrict__ bi, const float* __restrict__ bf,
                            const float* __restrict__ bg, const float* __restrict__ bo)
{
    int i = blockIdx.x * blockDim.x + threadIdx.x;
    if (i < E_ * G_) {
        int e = i / G_, j = i % G_;
        int g = j / H_, jj = j % H_;
        const float* U = (g == 0) ? Ui : (g == 1) ? Uf : (g == 2) ? Ug : Uo;
        g_Ucat[i] = U[e * H_ + jj];
    }
    if (i < H_ * G_) {
        int k = i / G_, j = i % G_;
        int g = j / H_, jj = j % H_;
        const float* W = (g == 0) ? Wi : (g == 1) ? Wf : (g == 2) ? Wg : Wo;
        g_Whcat[i] = W[k * H_ + jj];
    }
    if (i < G_) {
        int g = i / H_, jj = i % H_;
        const float* bb = (g == 0) ? bi : (g == 1) ? bf : (g == 2) ? bg : bo;
        g_bcat[i] = bb[jj];
    }
}

// ---------------- tiled SGEMM, 128x128 tile, BK=16, 256 thr, 8x8/thread ----
// MODE 0: xproj  = gather(embed, x_ind) @ Ucat + bcat   (M=4096,N=1024,K=512)
// MODE 1: logits = gather(hs)           @ W_hy + b_y    (M=4096,N=32000,K=256)
template <int MODE>
__global__ void sgemm_kernel(const float* __restrict__ A_ext,   // embed (mode0) / unused (mode1)
                             const float* __restrict__ B_ext,   // unused (mode0) / W_hy (mode1)
                             const float* __restrict__ bias_ext,// unused (mode0) / b_y  (mode1)
                             float* __restrict__ C_ext,         // unused (mode0) / d_out (mode1)
                             const int* __restrict__ xind)      // x_ind (mode0) / unused
{
    constexpr int N = (MODE == 0) ? G_ : V_;
    constexpr int K = (MODE == 0) ? E_ : H_;

    __shared__ float As[16][132];   // padded to dodge store conflicts
    __shared__ float Bs[16][128];

    const int tid  = threadIdx.x;
    const int row0 = blockIdx.y * 128;
    const int col0 = blockIdx.x * 128;

    const float* Bmat = (MODE == 0) ? g_Ucat : B_ext;
    const float* bias = (MODE == 0) ? g_bcat : bias_ext;
    float*       Cout = (MODE == 0) ? g_xproj : C_ext;

    // A tile load mapping: thread -> rows (tid/4, tid/4+64), k-offset (tid%4)*4
    const int a_r = tid >> 2;
    const int a_k = (tid & 3) * 4;
    const float* arow[2];
#pragma unroll
    for (int s = 0; s < 2; s++) {
        int r = row0 + a_r + s * 64;
        if (MODE == 0) {
            int t = r / B_, b = r % B_;
            arow[s] = A_ext + (size_t)xind[b * T_ + t] * E_;
        } else {
            int b = r / T_, t = r % T_;
            arow[s] = g_hs + (size_t)(t * B_ + b) * H_;
        }
    }

    // B tile load mapping: rows tid/32 (+8), cols (tid%32)*4
    const int b_r = tid >> 5;
    const int b_c = (tid & 31) * 4;

    float acc[8][8];
#pragma unroll
    for (int i = 0; i < 8; i++)
#pragma unroll
        for (int j = 0; j < 8; j++) acc[i][j] = 0.f;

    const int m0 = (tid >> 4) * 8;
    const int n0 = (tid & 15) * 8;

    for (int k0 = 0; k0 < K; k0 += 16) {
#pragma unroll
        for (int s = 0; s < 2; s++) {
            float4 v = *reinterpret_cast<const float4*>(arow[s] + k0 + a_k);
            int m = a_r + s * 64;
            As[a_k + 0][m] = v.x;
            As[a_k + 1][m] = v.y;
            As[a_k + 2][m] = v.z;
            As[a_k + 3][m] = v.w;
        }
#pragma unroll
        for (int s = 0; s < 2; s++) {
            int kk = b_r + s * 8;
            float4 v = *reinterpret_cast<const float4*>(
                Bmat + (size_t)(k0 + kk) * N + col0 + b_c);
            *reinterpret_cast<float4*>(&Bs[kk][b_c]) = v;
        }
        __syncthreads();

#pragma unroll
        for (int k = 0; k < 16; k++) {
            float a[8], b[8];
#pragma unroll
            for (int i = 0; i < 8; i++) a[i] = As[k][m0 + i];
#pragma unroll
            for (int j = 0; j < 8; j++) b[j] = Bs[k][n0 + j];
#pragma unroll
            for (int i = 0; i < 8; i++)
#pragma unroll
                for (int j = 0; j < 8; j++) acc[i][j] += a[i] * b[j];
        }
        __syncthreads();
    }

    // epilogue: add bias, write float4
#pragma unroll
    for (int i = 0; i < 8; i++) {
        size_t r = (size_t)(row0 + m0 + i);
#pragma unroll
        for (int j = 0; j < 8; j += 4) {
            float4 v;
            v.x = acc[i][j + 0] + bias[col0 + n0 + j + 0];
            v.y = acc[i][j + 1] + bias[col0 + n0 + j + 1];
            v.z = acc[i][j + 2] + bias[col0 + n0 + j + 2];
            v.w = acc[i][j + 3] + bias[col0 + n0 + j + 3];
            *reinterpret_cast<float4*>(Cout + r * N + col0 + n0 + j) = v;
        }
    }
}

// ---------------- LSTM recurrence: one CTA per batch element ----------------
__global__ void lstm_scan_kernel()
{
    const int b   = blockIdx.x;   // 0..31
    const int tid = threadIdx.x;  // 0..255, each owns 4 consecutive z-columns

    __shared__ float h_s[H_];
    __shared__ float c_s[H_];
    __shared__ float z_s[G_];

    if (tid < H_) { h_s[tid] = 0.f; c_s[tid] = 0.f; }
    __syncthreads();

    const int j4 = tid * 4;

    for (int t = 0; t < T_; t++) {
        const float* xp = g_xproj + (size_t)(t * B_ + b) * G_ + j4;
        float4 acc = *reinterpret_cast<const float4*>(xp);

#pragma unroll 4
        for (int k = 0; k < H_; k++) {
            float hk = h_s[k];
            float4 w = *reinterpret_cast<const float4*>(g_Whcat + (size_t)k * G_ + j4);
            acc.x += hk * w.x;
            acc.y += hk * w.y;
            acc.z += hk * w.z;
            acc.w += hk * w.w;
        }
        *reinterpret_cast<float4*>(&z_s[j4]) = acc;
        __syncthreads();   // all dots done (h_s reads complete), z_s visible

        if (tid < H_) {
            float zi = z_s[tid];
            float zf = z_s[tid + H_];
            float zg = z_s[tid + 2 * H_];
            float zo = z_s[tid + 3 * H_];
            float ig = 1.f / (1.f + expf(-zi));
            float fg = 1.f / (1.f + expf(-zf));
            float gg = tanhf(zg);
            float og = 1.f / (1.f + expf(-zo));
            float c  = fg * c_s[tid] + ig * gg;
            float h  = og * tanhf(c);
            c_s[tid] = c;
            h_s[tid] = h;
            g_hs[(size_t)(t * B_ + b) * H_ + tid] = h;
        }
        __syncthreads();   // h_s/c_s updated before next step's reads
    }
}

// ---------------- launch ----------------
extern "C" void kernel_launch(void* const* d_in, const int* in_sizes, int n_in,
                              void* d_out, int out_size)
{
    const int*   x_ind = (const int*)  d_in[0];
    const float* embed = (const float*)d_in[1];
    const float* U_i   = (const float*)d_in[2];
    const float* U_f   = (const float*)d_in[3];
    const float* U_g   = (const float*)d_in[4];
    const float* U_o   = (const float*)d_in[5];
    const float* W_i   = (const float*)d_in[6];
    const float* W_f   = (const float*)d_in[7];
    const float* W_g   = (const float*)d_in[8];
    const float* W_o   = (const float*)d_in[9];
    const float* b_i   = (const float*)d_in[10];
    const float* b_f   = (const float*)d_in[11];
    const float* b_g   = (const float*)d_in[12];
    const float* b_o   = (const float*)d_in[13];
    const float* W_hy  = (const float*)d_in[14];
    const float* b_y   = (const float*)d_in[15];
    float* out = (float*)d_out;

    // 1. pack concatenated gate weights
    {
        int total = E_ * G_;
        pack_kernel<<<(total + 255) / 256, 256>>>(U_i, U_f, U_g, U_o,
                                                  W_i, W_f, W_g, W_o,
                                                  b_i, b_f, b_g, b_o);
    }

    // 2. xproj[T][B][4H] = embed[x_ind] @ Ucat + bcat
    {
        dim3 grid(G_ / 128, (T_ * B_) / 128);  // (8, 32)
        sgemm_kernel<0><<<grid, 256>>>(embed, nullptr, nullptr, nullptr, x_ind);
    }

    // 3. LSTM recurrence over T
    lstm_scan_kernel<<<B_, 256>>>();

    // 4. logits[B][T][V] = hs @ W_hy + b_y
    {
        dim3 grid(V_ / 128, (T_ * B_) / 128);  // (250, 32)
        sgemm_kernel<1><<<grid, 256>>>(nullptr, W_hy, b_y, out, nullptr);
    }
}

// round 4
// speedup vs baseline: 1.3640x; 1.3640x over previous
#include <cuda_runtime.h>
#include <cuda_bf16.h>
#include <math.h>
#include <stdint.h>

#define B_ 32
#define T_ 128
#define E_ 512
#define H_ 256
#define V_ 32000
#define G_ 1024  // 4*H

// ---------------- scratch (device globals; no allocations) ----------------
__device__ float g_Ucat[E_ * G_];        // [E][4H]   2 MB
__device__ float g_Whcat[H_ * G_];       // [H][4H]   1 MB
__device__ float g_bcat[G_];             // [4H]
__device__ float g_xproj[T_ * B_ * G_];  // [T][B][4H] 16 MB
__device__ __nv_bfloat16 g_Ahi[B_ * T_ * H_];   // hs split, [B*T][H] 2 MB
__device__ __nv_bfloat16 g_Alo[B_ * T_ * H_];
__device__ __nv_bfloat16 g_Bthi[V_ * H_];       // W_hy^T split, [V][H] 16 MB
__device__ __nv_bfloat16 g_Btlo[V_ * H_];

// ======================= PTX helpers (sm_80-class only) =====================
__device__ __forceinline__ uint32_t smem_u32(const void* p) {
    uint32_t a;
    asm("{ .reg .u64 t; cvta.to.shared.u64 t, %1; cvt.u32.u64 %0, t; }"
        : "=r"(a) : "l"(p));
    return a;
}

__device__ __forceinline__ void cp_async16(uint32_t saddr, const void* gaddr) {
    asm volatile("cp.async.cg.shared.global [%0], [%1], 16;"
                 :: "r"(saddr), "l"(gaddr) : "memory");
}
__device__ __forceinline__ void cp_commit() {
    asm volatile("cp.async.commit_group;" ::: "memory");
}
template <int N>
__device__ __forceinline__ void cp_wait() {
    asm volatile("cp.async.wait_group %0;" :: "n"(N) : "memory");
}

__device__ __forceinline__ void ldsm_x4(uint32_t& r0, uint32_t& r1,
                                        uint32_t& r2, uint32_t& r3, uint32_t a) {
    asm volatile("ldmatrix.sync.aligned.m8n8.x4.shared.b16 {%0,%1,%2,%3}, [%4];"
                 : "=r"(r0), "=r"(r1), "=r"(r2), "=r"(r3) : "r"(a));
}
__device__ __forceinline__ void ldsm_x2(uint32_t& r0, uint32_t& r1, uint32_t a) {
    asm volatile("ldmatrix.sync.aligned.m8n8.x2.shared.b16 {%0,%1}, [%2];"
                 : "=r"(r0), "=r"(r1) : "r"(a));
}

__device__ __forceinline__ void mma_bf16(float* d, const uint32_t* a,
                                         const uint32_t* b) {
    asm volatile(
        "mma.sync.aligned.m16n8k16.row.col.f32.bf16.bf16.f32 "
        "{%0,%1,%2,%3}, {%4,%5,%6,%7}, {%8,%9}, {%0,%1,%2,%3};"
        : "+f"(d[0]), "+f"(d[1]), "+f"(d[2]), "+f"(d[3])
        : "r"(a[0]), "r"(a[1]), "r"(a[2]), "r"(a[3]), "r"(b[0]), "r"(b[1]));
}

// ---------------- pack gate weights into concatenated layout ----------------
__global__ void pack_kernel(const float* __restrict__ Ui, const float* __restrict__ Uf,
                            const float* __restrict__ Ug, const float* __restrict__ Uo,
                            const float* __restrict__ Wi, const float* __restrict__ Wf,
                            const float* __restrict__ Wg, const float* __restrict__ Wo,
                            const float* __restrict__ bi, const float* __restrict__ bf,
                            const float* __restrict__ bg, const float* __restrict__ bo)
{
    int i = blockIdx.x * blockDim.x + threadIdx.x;
    if (i < E_ * G_) {
        int e = i / G_, j = i % G_;
        int g = j / H_, jj = j % H_;
        const float* U = (g == 0) ? Ui : (g == 1) ? Uf : (g == 2) ? Ug : Uo;
        g_Ucat[i] = U[e * H_ + jj];
    }
    if (i < H_ * G_) {
        int k = i / G_, j = i % G_;
        int g = j / H_, jj = j % H_;
        const float* W = (g == 0) ? Wi : (g == 1) ? Wf : (g == 2) ? Wg : Wo;
        g_Whcat[i] = W[k * H_ + jj];
    }
    if (i < G_) {
        int g = i / H_, jj = i % H_;
        const float* bb = (g == 0) ? bi : (g == 1) ? bf : (g == 2) ? bg : bo;
        g_bcat[i] = bb[jj];
    }
}

// --------- transpose + bf16-split W_hy [H][V] -> Bt_hi/Bt_lo [V][H] ---------
__global__ void convW_kernel(const float* __restrict__ W_hy)
{
    __shared__ float tl[32][33];
    int v0 = blockIdx.x * 32, k0 = blockIdx.y * 32;
    int tx = threadIdx.x, ty = threadIdx.y;
#pragma unroll
    for (int i = 0; i < 4; i++) {
        int k = ty + i * 8;
        tl[k][tx] = W_hy[(size_t)(k0 + k) * V_ + v0 + tx];
    }
    __syncthreads();
#pragma unroll
    for (int i = 0; i < 4; i++) {
        int vr = ty + i * 8;
        float x = tl[tx][vr];
        __nv_bfloat16 hi = __float2bfloat16(x);
        __nv_bfloat16 lo = __float2bfloat16(x - __bfloat162float(hi));
        size_t o = (size_t)(v0 + vr) * H_ + k0 + tx;
        g_Bthi[o] = hi;
        g_Btlo[o] = lo;
    }
}

// ---------------- fp32 SGEMM for xproj (M=4096,N=1024,K=512) ----------------
__global__ void sgemm_xproj(const float* __restrict__ embed,
                            const int* __restrict__ xind)
{
    constexpr int N = G_;
    constexpr int K = E_;
    __shared__ float As[16][132];
    __shared__ float Bs[16][128];

    const int tid  = threadIdx.x;
    const int row0 = blockIdx.y * 128;
    const int col0 = blockIdx.x * 128;

    const int a_r = tid >> 2;
    const int a_k = (tid & 3) * 4;
    const float* arow[2];
#pragma unroll
    for (int s = 0; s < 2; s++) {
        int r = row0 + a_r + s * 64;
        int t = r / B_, b = r % B_;
        arow[s] = embed + (size_t)xind[b * T_ + t] * E_;
    }
    const int b_r = tid >> 5;
    const int b_c = (tid & 31) * 4;

    float acc[8][8];
#pragma unroll
    for (int i = 0; i < 8; i++)
#pragma unroll
        for (int j = 0; j < 8; j++) acc[i][j] = 0.f;

    const int m0 = (tid >> 4) * 8;
    const int n0 = (tid & 15) * 8;

    for (int k0 = 0; k0 < K; k0 += 16) {
#pragma unroll
        for (int s = 0; s < 2; s++) {
            float4 v = *reinterpret_cast<const float4*>(arow[s] + k0 + a_k);
            int m = a_r + s * 64;
            As[a_k + 0][m] = v.x; As[a_k + 1][m] = v.y;
            As[a_k + 2][m] = v.z; As[a_k + 3][m] = v.w;
        }
#pragma unroll
        for (int s = 0; s < 2; s++) {
            int kk = b_r + s * 8;
            float4 v = *reinterpret_cast<const float4*>(
                g_Ucat + (size_t)(k0 + kk) * N + col0 + b_c);
            *reinterpret_cast<float4*>(&Bs[kk][b_c]) = v;
        }
        __syncthreads();
#pragma unroll
        for (int k = 0; k < 16; k++) {
            float a[8], b[8];
#pragma unroll
            for (int i = 0; i < 8; i++) a[i] = As[k][m0 + i];
#pragma unroll
            for (int j = 0; j < 8; j++) b[j] = Bs[k][n0 + j];
#pragma unroll
            for (int i = 0; i < 8; i++)
#pragma unroll
                for (int j = 0; j < 8; j++) acc[i][j] += a[i] * b[j];
        }
        __syncthreads();
    }
#pragma unroll
    for (int i = 0; i < 8; i++) {
        size_t r = (size_t)(row0 + m0 + i);
#pragma unroll
        for (int j = 0; j < 8; j += 4) {
            float4 v;
            v.x = acc[i][j + 0] + g_bcat[col0 + n0 + j + 0];
            v.y = acc[i][j + 1] + g_bcat[col0 + n0 + j + 1];
            v.z = acc[i][j + 2] + g_bcat[col0 + n0 + j + 2];
            v.w = acc[i][j + 3] + g_bcat[col0 + n0 + j + 3];
            *reinterpret_cast<float4*>(g_xproj + r * N + col0 + n0 + j) = v;
        }
    }
}

// ---------------- LSTM recurrence: one CTA per batch element ----------------
__global__ void lstm_scan_kernel()
{
    const int b   = blockIdx.x;
    const int tid = threadIdx.x;  // 0..255

    __shared__ float h_s[H_];
    __shared__ float c_s[H_];
    __shared__ float z_s[G_];

    h_s[tid & (H_ - 1)] = 0.f;
    c_s[tid & (H_ - 1)] = 0.f;
    __syncthreads();

    const int j4 = tid * 4;

    for (int t = 0; t < T_; t++) {
        const float* xp = g_xproj + (size_t)(t * B_ + b) * G_ + j4;
        float4 acc = *reinterpret_cast<const float4*>(xp);

#pragma unroll 4
        for (int k = 0; k < H_; k++) {
            float hk = h_s[k];
            float4 w = *reinterpret_cast<const float4*>(g_Whcat + (size_t)k * G_ + j4);
            acc.x += hk * w.x;
            acc.y += hk * w.y;
            acc.z += hk * w.z;
            acc.w += hk * w.w;
        }
        *reinterpret_cast<float4*>(&z_s[j4]) = acc;
        __syncthreads();

        {
            float zi = z_s[tid];
            float zf = z_s[tid + H_];
            float zg = z_s[tid + 2 * H_];
            float zo = z_s[tid + 3 * H_];
            float ig = 1.f / (1.f + expf(-zi));
            float fg = 1.f / (1.f + expf(-zf));
            float gg = tanhf(zg);
            float og = 1.f / (1.f + expf(-zo));
            float c  = fg * c_s[tid] + ig * gg;
            float h  = og * tanhf(c);
            c_s[tid] = c;
            h_s[tid] = h;
            __nv_bfloat16 hi = __float2bfloat16(h);
            __nv_bfloat16 lo = __float2bfloat16(h - __bfloat162float(hi));
            size_t o = (size_t)(b * T_ + t) * H_ + tid;
            g_Ahi[o] = hi;
            g_Alo[o] = lo;
        }
        __syncthreads();
    }
}

// ======== GEMM2: logits = (Ahi+Alo) @ (Bhi+Blo)^T via mma.sync bf16 =========
// 128x128 CTA tile, K=256 in 8 stages of BK=32, cp.async double-buffered.
// 8 warps in 2x4 layout; each warp computes 64x32 via m16n8k16 (3-term split).
#define BK 32
#define SROW 40                       // padded row stride (bf16 elems) = 80B
#define TILE_SB (128 * SROW * 2)      // 10240 B per matrix per stage
#define STAGE_SB (4 * TILE_SB)        // Ahi,Alo,Bhi,Blo
#define GEMM2_SMEM (2 * STAGE_SB)     // 81920 B

__global__ __launch_bounds__(256) void gemm2_kernel(
    float* __restrict__ out, const float* __restrict__ b_y)
{
    extern __shared__ char smem[];
    const uint32_t sb = smem_u32(smem);
    const int tid  = threadIdx.x;
    const int lane = tid & 31;
    const int wid  = tid >> 5;
    const int wm   = wid >> 2;   // 0..1 -> 64-row half
    const int wn   = wid & 3;    // 0..3 -> 32-col quarter

    const int row0 = blockIdx.y * 128;   // M tile (b*T+t)
    const int col0 = blockIdx.x * 128;   // V tile

    // ---- cp.async staging mapping: thread -> 2 rows x 16B per matrix ----
    const int ld_r   = tid >> 2;          // 0..63
    const int ld_seg = tid & 3;           // 16B segment within 64B row chunk
    const __nv_bfloat16* gsrc[4];
    gsrc[0] = g_Ahi  + (size_t)(row0)*H_;
    gsrc[1] = g_Alo  + (size_t)(row0)*H_;
    gsrc[2] = g_Bthi + (size_t)(col0)*H_;
    gsrc[3] = g_Btlo + (size_t)(col0)*H_;

    float acc[4][4][4];
#pragma unroll
    for (int i = 0; i < 4; i++)
#pragma unroll
        for (int j = 0; j < 4; j++)
#pragma unroll
            for (int r = 0; r < 4; r++) acc[i][j][r] = 0.f;

    // prefetch stage 0
#pragma unroll
    for (int m = 0; m < 4; m++)
#pragma unroll
        for (int h = 0; h < 2; h++) {
            int r = ld_r + h * 64;
            uint32_t sa = sb + 0 * STAGE_SB + m * TILE_SB + r * (SROW * 2) + ld_seg * 16;
            cp_async16(sa, gsrc[m] + (size_t)r * H_ + 0 * BK + ld_seg * 8);
        }
    cp_commit();

    for (int s = 0; s < 8; s++) {
        if (s + 1 < 8) {
            int buf = (s + 1) & 1;
#pragma unroll
            for (int m = 0; m < 4; m++)
#pragma unroll
                for (int h = 0; h < 2; h++) {
                    int r = ld_r + h * 64;
                    uint32_t sa = sb + buf * STAGE_SB + m * TILE_SB +
                                  r * (SROW * 2) + ld_seg * 16;
                    cp_async16(sa, gsrc[m] + (size_t)r * H_ + (s + 1) * BK + ld_seg * 8);
                }
            cp_commit();
            cp_wait<1>();
        } else {
            cp_wait<0>();
        }
        __syncthreads();

        const uint32_t base = sb + (s & 1) * STAGE_SB;
        const uint32_t sAhi = base;
        const uint32_t sAlo = base + TILE_SB;
        const uint32_t sBhi = base + 2 * TILE_SB;
        const uint32_t sBlo = base + 3 * TILE_SB;

#pragma unroll
        for (int kk = 0; kk < 2; kk++) {
            uint32_t ahi[4][4], alo[4][4], bhi[4][2], blo[4][2];
            // A fragments: 4 m-tiles of 16 rows
            const int a_row_l = (lane & 15);
            const int a_col   = kk * 16 + (lane >> 4) * 8;
#pragma unroll
            for (int mt = 0; mt < 4; mt++) {
                int r = wm * 64 + mt * 16 + a_row_l;
                uint32_t off = (uint32_t)(r * (SROW * 2) + a_col * 2);
                ldsm_x4(ahi[mt][0], ahi[mt][1], ahi[mt][2], ahi[mt][3], sAhi + off);
                ldsm_x4(alo[mt][0], alo[mt][1], alo[mt][2], alo[mt][3], sAlo + off);
            }
            // B fragments: 4 n-tiles of 8 rows (Bt row-major = col-major B)
            const int b_row_l = (lane & 7);
            const int b_col   = kk * 16 + ((lane >> 3) & 1) * 8;
#pragma unroll
            for (int nt = 0; nt < 4; nt++) {
                int r = wn * 32 + nt * 8 + b_row_l;
                uint32_t off = (uint32_t)(r * (SROW * 2) + b_col * 2);
                ldsm_x2(bhi[nt][0], bhi[nt][1], sBhi + off);
                ldsm_x2(blo[nt][0], blo[nt][1], sBlo + off);
            }
#pragma unroll
            for (int mt = 0; mt < 4; mt++)
#pragma unroll
                for (int nt = 0; nt < 4; nt++) {
                    mma_bf16(acc[mt][nt], ahi[mt], bhi[nt]);
                    mma_bf16(acc[mt][nt], ahi[mt], blo[nt]);
                    mma_bf16(acc[mt][nt], alo[mt], bhi[nt]);
                }
        }
        __syncthreads();
    }

    // ---- epilogue: fragment -> gmem with bias ----
    const int er = lane >> 2;         // 0..7
    const int ec = (lane & 3) * 2;    // 0,2,4,6
#pragma unroll
    for (int mt = 0; mt < 4; mt++) {
#pragma unroll
        for (int nt = 0; nt < 4; nt++) {
            int col = col0 + wn * 32 + nt * 8 + ec;
            float bx = b_y[col], by = b_y[col + 1];
            int r0 = row0 + wm * 64 + mt * 16 + er;
            float2 v0 = make_float2(acc[mt][nt][0] + bx, acc[mt][nt][1] + by);
            float2 v1 = make_float2(acc[mt][nt][2] + bx, acc[mt][nt][3] + by);
            *reinterpret_cast<float2*>(out + (size_t)r0 * V_ + col) = v0;
            *reinterpret_cast<float2*>(out + (size_t)(r0 + 8) * V_ + col) = v1;
        }
    }
}

// ---------------- launch ----------------
extern "C" void kernel_launch(void* const* d_in, const int* in_sizes, int n_in,
                              void* d_out, int out_size)
{
    const int*   x_ind = (const int*)  d_in[0];
    const float* embed = (const float*)d_in[1];
    const float* U_i   = (const float*)d_in[2];
    const float* U_f   = (const float*)d_in[3];
    const float* U_g   = (const float*)d_in[4];
    const float* U_o   = (const float*)d_in[5];
    const float* W_i   = (const float*)d_in[6];
    const float* W_f   = (const float*)d_in[7];
    const float* W_g   = (const float*)d_in[8];
    const float* W_o   = (const float*)d_in[9];
    const float* b_i   = (const float*)d_in[10];
    const float* b_f   = (const float*)d_in[11];
    const float* b_g   = (const float*)d_in[12];
    const float* b_o   = (const float*)d_in[13];
    const float* W_hy  = (const float*)d_in[14];
    const float* b_y   = (const float*)d_in[15];
    float* out = (float*)d_out;

    cudaFuncSetAttribute(gemm2_kernel,
                         cudaFuncAttributeMaxDynamicSharedMemorySize, GEMM2_SMEM);

    // 1. pack concatenated gate weights
    {
        int total = E_ * G_;
        pack_kernel<<<(total + 255) / 256, 256>>>(U_i, U_f, U_g, U_o,
                                                  W_i, W_f, W_g, W_o,
                                                  b_i, b_f, b_g, b_o);
    }

    // 2. transpose + split W_hy for the tensor-core logits GEMM
    {
        dim3 grid(V_ / 32, H_ / 32);  // (1000, 8)
        dim3 blk(32, 8);
        convW_kernel<<<grid, blk>>>(W_hy);
    }

    // 3. xproj[T][B][4H] = embed[x_ind] @ Ucat + bcat
    {
        dim3 grid(G_ / 128, (T_ * B_) / 128);  // (8, 32)
        sgemm_xproj<<<grid, 256>>>(embed, x_ind);
    }

    // 4. LSTM recurrence over T (emits bf16-split hs)
    lstm_scan_kernel<<<B_, 256>>>();

    // 5. logits[B][T][V] = hs @ W_hy + b_y  (mma.sync bf16, 3-term split)
    {
        dim3 grid(V_ / 128, (B_ * T_) / 128);  // (250, 32)
        gemm2_kernel<<<grid, 256, GEMM2_SMEM>>>(out, b_y);
    }
}

// round 5
// speedup vs baseline: 2.8280x; 2.0732x over previous
#include <cuda_runtime.h>
#include <cuda_bf16.h>
#include <math.h>
#include <stdint.h>

#define B_ 32
#define T_ 128
#define E_ 512
#define H_ 256
#define V_ 32000
#define G_ 1024  // 4*H

// ---------------- scratch (device globals; no allocations) ----------------
__device__ float g_Ucat[E_ * G_];        // [E][4H]   2 MB
__device__ float g_Whcat[H_ * G_];       // [H][4H]   1 MB
__device__ float g_bcat[G_];             // [4H]
__device__ float g_xproj[T_ * B_ * G_];  // [T][B][4H] 16 MB
__device__ __nv_bfloat16 g_Ahi[B_ * T_ * H_];   // hs split, [B*T][H] 2 MB
__device__ __nv_bfloat16 g_Alo[B_ * T_ * H_];
__device__ __nv_bfloat16 g_Bthi[V_ * H_];       // W_hy^T split, [V][H] 16 MB
__device__ __nv_bfloat16 g_Btlo[V_ * H_];

// ======================= PTX helpers (sm_90-base only) =====================
__device__ __forceinline__ uint32_t smem_u32(const void* p) {
    uint32_t a;
    asm("{ .reg .u64 t; cvta.to.shared.u64 t, %1; cvt.u32.u64 %0, t; }"
        : "=r"(a) : "l"(p));
    return a;
}

__device__ __forceinline__ void cp_async16(uint32_t saddr, const void* gaddr) {
    asm volatile("cp.async.cg.shared.global [%0], [%1], 16;"
                 :: "r"(saddr), "l"(gaddr) : "memory");
}
__device__ __forceinline__ void cp_commit() {
    asm volatile("cp.async.commit_group;" ::: "memory");
}
template <int N>
__device__ __forceinline__ void cp_wait() {
    asm volatile("cp.async.wait_group %0;" :: "n"(N) : "memory");
}

__device__ __forceinline__ void ldsm_x4(uint32_t& r0, uint32_t& r1,
                                        uint32_t& r2, uint32_t& r3, uint32_t a) {
    asm volatile("ldmatrix.sync.aligned.m8n8.x4.shared.b16 {%0,%1,%2,%3}, [%4];"
                 : "=r"(r0), "=r"(r1), "=r"(r2), "=r"(r3) : "r"(a));
}
__device__ __forceinline__ void ldsm_x2(uint32_t& r0, uint32_t& r1, uint32_t a) {
    asm volatile("ldmatrix.sync.aligned.m8n8.x2.shared.b16 {%0,%1}, [%2];"
                 : "=r"(r0), "=r"(r1) : "r"(a));
}

__device__ __forceinline__ void mma_bf16(float* d, const uint32_t* a,
                                         const uint32_t* b) {
    asm volatile(
        "mma.sync.aligned.m16n8k16.row.col.f32.bf16.bf16.f32 "
        "{%0,%1,%2,%3}, {%4,%5,%6,%7}, {%8,%9}, {%0,%1,%2,%3};"
        : "+f"(d[0]), "+f"(d[1]), "+f"(d[2]), "+f"(d[3])
        : "r"(a[0]), "r"(a[1]), "r"(a[2]), "r"(a[3]), "r"(b[0]), "r"(b[1]));
}

#define CLUSTER_SYNC() do { \
    asm volatile("barrier.cluster.arrive.aligned;" ::: "memory"); \
    asm volatile("barrier.cluster.wait.aligned;" ::: "memory"); \
} while (0)

__device__ __forceinline__ uint32_t mapa_cluster(uint32_t local, uint32_t rank) {
    uint32_t r;
    asm volatile("mapa.shared::cluster.u32 %0, %1, %2;" : "=r"(r) : "r"(local), "r"(rank));
    return r;
}
__device__ __forceinline__ void st_cluster_f32(uint32_t addr, float v) {
    asm volatile("st.shared::cluster.f32 [%0], %1;" :: "r"(addr), "f"(v) : "memory");
}

// ---------------- pack gate weights into concatenated layout ----------------
__global__ void pack_kernel(const float* __restrict__ Ui, const float* __restrict__ Uf,
                            const float* __restrict__ Ug, const float* __restrict__ Uo,
                            const float* __restrict__ Wi, const float* __restrict__ Wf,
                            const float* __restrict__ Wg, const float* __restrict__ Wo,
                            const float* __restrict__ bi, const float* __restrict__ bf,
                            const float* __restrict__ bg, const float* __restrict__ bo)
{
    int i = blockIdx.x * blockDim.x + threadIdx.x;
    if (i < E_ * G_) {
        int e = i / G_, j = i % G_;
        int g = j / H_, jj = j % H_;
        const float* U = (g == 0) ? Ui : (g == 1) ? Uf : (g == 2) ? Ug : Uo;
        g_Ucat[i] = U[e * H_ + jj];
    }
    if (i < H_ * G_) {
        int k = i / G_, j = i % G_;
        int g = j / H_, jj = j % H_;
        const float* W = (g == 0) ? Wi : (g == 1) ? Wf : (g == 2) ? Wg : Wo;
        g_Whcat[i] = W[k * H_ + jj];
    }
    if (i < G_) {
        int g = i / H_, jj = i % H_;
        const float* bb = (g == 0) ? bi : (g == 1) ? bf : (g == 2) ? bg : bo;
        g_bcat[i] = bb[jj];
    }
}

// --------- transpose + bf16-split W_hy [H][V] -> Bt_hi/Bt_lo [V][H] ---------
__global__ void convW_kernel(const float* __restrict__ W_hy)
{
    __shared__ float tl[32][33];
    int v0 = blockIdx.x * 32, k0 = blockIdx.y * 32;
    int tx = threadIdx.x, ty = threadIdx.y;
#pragma unroll
    for (int i = 0; i < 4; i++) {
        int k = ty + i * 8;
        tl[k][tx] = W_hy[(size_t)(k0 + k) * V_ + v0 + tx];
    }
    __syncthreads();
#pragma unroll
    for (int i = 0; i < 4; i++) {
        int vr = ty + i * 8;
        float x = tl[tx][vr];
        __nv_bfloat16 hi = __float2bfloat16(x);
        __nv_bfloat16 lo = __float2bfloat16(x - __bfloat162float(hi));
        size_t o = (size_t)(v0 + vr) * H_ + k0 + tx;
        g_Bthi[o] = hi;
        g_Btlo[o] = lo;
    }
}

// ---------------- fp32 SGEMM for xproj (M=4096,N=1024,K=512) ----------------
__global__ void sgemm_xproj(const float* __restrict__ embed,
                            const int* __restrict__ xind)
{
    constexpr int N = G_;
    constexpr int K = E_;
    __shared__ float As[16][132];
    __shared__ float Bs[16][128];

    const int tid  = threadIdx.x;
    const int row0 = blockIdx.y * 128;
    const int col0 = blockIdx.x * 128;

    const int a_r = tid >> 2;
    const int a_k = (tid & 3) * 4;
    const float* arow[2];
#pragma unroll
    for (int s = 0; s < 2; s++) {
        int r = row0 + a_r + s * 64;
        int t = r / B_, b = r % B_;
        arow[s] = embed + (size_t)xind[b * T_ + t] * E_;
    }
    const int b_r = tid >> 5;
    const int b_c = (tid & 31) * 4;

    float acc[8][8];
#pragma unroll
    for (int i = 0; i < 8; i++)
#pragma unroll
        for (int j = 0; j < 8; j++) acc[i][j] = 0.f;

    const int m0 = (tid >> 4) * 8;
    const int n0 = (tid & 15) * 8;

    for (int k0 = 0; k0 < K; k0 += 16) {
#pragma unroll
        for (int s = 0; s < 2; s++) {
            float4 v = *reinterpret_cast<const float4*>(arow[s] + k0 + a_k);
            int m = a_r + s * 64;
            As[a_k + 0][m] = v.x; As[a_k + 1][m] = v.y;
            As[a_k + 2][m] = v.z; As[a_k + 3][m] = v.w;
        }
#pragma unroll
        for (int s = 0; s < 2; s++) {
            int kk = b_r + s * 8;
            float4 v = *reinterpret_cast<const float4*>(
                g_Ucat + (size_t)(k0 + kk) * N + col0 + b_c);
            *reinterpret_cast<float4*>(&Bs[kk][b_c]) = v;
        }
        __syncthreads();
#pragma unroll
        for (int k = 0; k < 16; k++) {
            float a[8], b[8];
#pragma unroll
            for (int i = 0; i < 8; i++) a[i] = As[k][m0 + i];
#pragma unroll
            for (int j = 0; j < 8; j++) b[j] = Bs[k][n0 + j];
#pragma unroll
            for (int i = 0; i < 8; i++)
#pragma unroll
                for (int j = 0; j < 8; j++) acc[i][j] += a[i] * b[j];
        }
        __syncthreads();
    }
#pragma unroll
    for (int i = 0; i < 8; i++) {
        size_t r = (size_t)(row0 + m0 + i);
#pragma unroll
        for (int j = 0; j < 8; j += 4) {
            float4 v;
            v.x = acc[i][j + 0] + g_bcat[col0 + n0 + j + 0];
            v.y = acc[i][j + 1] + g_bcat[col0 + n0 + j + 1];
            v.z = acc[i][j + 2] + g_bcat[col0 + n0 + j + 2];
            v.w = acc[i][j + 3] + g_bcat[col0 + n0 + j + 3];
            *reinterpret_cast<float4*>(g_xproj + r * N + col0 + n0 + j) = v;
        }
    }
}

// ============ LSTM recurrence: cluster of 8 CTAs, 2 batches/cluster =========
// Each CTA owns h-slice [rank*32, rank*32+32) -> 128 z-cols (4 gates x 32),
// weight slice (256x128 fp32 = 128KB) resident in smem.
// Per step: smem dot -> reduce -> gates -> DSMEM h-broadcast -> cluster sync.
#define CL_C 8
#define NB 2
// smem float offsets
#define OFF_W   0                 // [256][128]
#define OFF_H   32768             // [2][NB][256] double-buffered full h
#define OFF_ZP  (OFF_H + 2*NB*256)   // [4][NB][128] partials
#define OFF_Z   (OFF_ZP + 4*NB*128)  // [NB][128]
#define OFF_STG (OFF_Z + NB*128)     // [NB*32] new-h staging
#define SCAN_SMEM_FLOATS (OFF_STG + NB*32)
#define SCAN_SMEM_BYTES (SCAN_SMEM_FLOATS * 4)

__global__ void __cluster_dims__(CL_C, 1, 1) __launch_bounds__(128, 1)
lstm_scan_cluster()
{
    extern __shared__ float sm[];
    float* w_s  = sm + OFF_W;
    float* h_s  = sm + OFF_H;
    float* zp_s = sm + OFF_ZP;
    float* z_s  = sm + OFF_Z;
    float* stg  = sm + OFF_STG;

    const int tid = threadIdx.x;  // 0..127
    uint32_t rank;
    asm("mov.u32 %0, %%cluster_ctarank;" : "=r"(rank));
    const int cid = blockIdx.x / CL_C;   // cluster id 0..15

    // preload weight slice: w_s[k][gate*32+c] = Whcat[k][gate*256 + rank*32 + c]
    for (int flat = tid; flat < 8192; flat += 128) {
        int c4 = flat & 7, gate = (flat >> 3) & 3, k = flat >> 5;
        float4 v = *reinterpret_cast<const float4*>(
            g_Whcat + (size_t)k * G_ + gate * H_ + rank * 32 + c4 * 4);
        *reinterpret_cast<float4*>(w_s + k * 128 + gate * 32 + c4 * 4) = v;
    }
    // init h buffer 0 (full h, both batches)
    for (int i = tid; i < NB * 256; i += 128) h_s[i] = 0.f;
    __syncthreads();
    CLUSTER_SYNC();

    const int kq = tid >> 5;   // warp: k-range [kq*64, kq*64+64)
    const int gg = tid & 31;   // 4-col group (cols 4gg..4gg+3 of CTA's 128)

    // gate-phase identity (threads 0..63)
    const int gb = tid >> 5;   // batch 0/1 (valid when tid<64)
    const int gc = tid & 31;   // slice col
    float c_reg = 0.f;

    for (int t = 0; t < T_; t++) {
        const int p = t & 1;
        const float* hb = h_s + p * (NB * 256);

        // prefetch xproj contribution (threads 0..63), overlap with dot
        float4 xp4 = make_float4(0.f, 0.f, 0.f, 0.f);
        if (tid < 64) {
            int bgl = cid * NB + gb;
            int gcol = (gc >> 3) * H_ + rank * 32 + 4 * (gc & 7);
            xp4 = *reinterpret_cast<const float4*>(
                g_xproj + (size_t)(t * B_ + bgl) * G_ + gcol);
        }

        // ---- dot: acc[b] = sum_k h[b][k] * w[k][4gg..] over this warp's k ----
        float4 a0 = make_float4(0.f, 0.f, 0.f, 0.f);
        float4 a1 = make_float4(0.f, 0.f, 0.f, 0.f);
        const float* wp = w_s + (kq * 64) * 128 + gg * 4;
        const float* h0 = hb + kq * 64;
        const float* h1 = hb + 256 + kq * 64;
#pragma unroll 4
        for (int k4 = 0; k4 < 16; k4++) {
            float4 hv0 = *reinterpret_cast<const float4*>(h0 + k4 * 4);
            float4 hv1 = *reinterpret_cast<const float4*>(h1 + k4 * 4);
#pragma unroll
            for (int kk = 0; kk < 4; kk++) {
                float4 w4 = *reinterpret_cast<const float4*>(wp + (k4 * 4 + kk) * 128);
                float e0 = (kk == 0) ? hv0.x : (kk == 1) ? hv0.y : (kk == 2) ? hv0.z : hv0.w;
                float e1 = (kk == 0) ? hv1.x : (kk == 1) ? hv1.y : (kk == 2) ? hv1.z : hv1.w;
                a0.x += e0 * w4.x; a0.y += e0 * w4.y; a0.z += e0 * w4.z; a0.w += e0 * w4.w;
                a1.x += e1 * w4.x; a1.y += e1 * w4.y; a1.z += e1 * w4.z; a1.w += e1 * w4.w;
            }
        }
        *reinterpret_cast<float4*>(zp_s + (kq * NB + 0) * 128 + gg * 4) = a0;
        *reinterpret_cast<float4*>(zp_s + (kq * NB + 1) * 128 + gg * 4) = a1;
        __syncthreads();

        // ---- reduce partials + xp -> z_s (threads 0..63) ----
        if (tid < 64) {
            float4 z4 = xp4;
#pragma unroll
            for (int q = 0; q < 4; q++) {
                float4 v = *reinterpret_cast<const float4*>(
                    zp_s + (q * NB + gb) * 128 + gc * 4);
                z4.x += v.x; z4.y += v.y; z4.z += v.z; z4.w += v.w;
            }
            *reinterpret_cast<float4*>(z_s + gb * 128 + gc * 4) = z4;
        }
        __syncthreads();

        // ---- gates (threads 0..63: (gb, gc)) ----
        if (tid < 64) {
            float zi = z_s[gb * 128 + gc];
            float zf = z_s[gb * 128 + 32 + gc];
            float zg = z_s[gb * 128 + 64 + gc];
            float zo = z_s[gb * 128 + 96 + gc];
            float ig = 1.f / (1.f + expf(-zi));
            float fg = 1.f / (1.f + expf(-zf));
            float gv = tanhf(zg);
            float og = 1.f / (1.f + expf(-zo));
            c_reg = fg * c_reg + ig * gv;
            float h = og * tanhf(c_reg);
            stg[gb * 32 + gc] = h;
            // bf16 hi/lo output for logits GEMM
            __nv_bfloat16 hi = __float2bfloat16(h);
            __nv_bfloat16 lo = __float2bfloat16(h - __bfloat162float(hi));
            int bgl = cid * NB + gb;
            size_t o = (size_t)(bgl * T_ + t) * H_ + rank * 32 + gc;
            g_Ahi[o] = hi;
            g_Alo[o] = lo;
        }
        __syncthreads();

        // ---- broadcast new h slice to all 8 CTAs' next h buffer ----
        {
            const int q = p ^ 1;
            for (int it = tid; it < CL_C * NB * 32; it += 128) {
                int rk = it >> 6;          // 0..7
                int b  = (it >> 5) & 1;
                int c  = it & 31;
                float v = stg[b * 32 + c];
                uint32_t la = smem_u32(h_s + q * (NB * 256) + b * 256 + rank * 32 + c);
                st_cluster_f32(mapa_cluster(la, (uint32_t)rk), v);
            }
        }
        CLUSTER_SYNC();
    }
}

// ======== GEMM2: logits = (Ahi+Alo) @ (Bhi+Blo)^T via mma.sync bf16 =========
#define BK 32
#define SROW 40                       // padded row stride (bf16 elems) = 80B
#define TILE_SB (128 * SROW * 2)      // 10240 B per matrix per stage
#define STAGE_SB (4 * TILE_SB)        // Ahi,Alo,Bhi,Blo
#define GEMM2_SMEM (2 * STAGE_SB)     // 81920 B

__global__ __launch_bounds__(256) void gemm2_kernel(
    float* __restrict__ out, const float* __restrict__ b_y)
{
    extern __shared__ char smem[];
    const uint32_t sb = smem_u32(smem);
    const int tid  = threadIdx.x;
    const int lane = tid & 31;
    const int wid  = tid >> 5;
    const int wm   = wid >> 2;
    const int wn   = wid & 3;

    const int row0 = blockIdx.y * 128;
    const int col0 = blockIdx.x * 128;

    const int ld_r   = tid >> 2;
    const int ld_seg = tid & 3;
    const __nv_bfloat16* gsrc[4];
    gsrc[0] = g_Ahi  + (size_t)(row0)*H_;
    gsrc[1] = g_Alo  + (size_t)(row0)*H_;
    gsrc[2] = g_Bthi + (size_t)(col0)*H_;
    gsrc[3] = g_Btlo + (size_t)(col0)*H_;

    float acc[4][4][4];
#pragma unroll
    for (int i = 0; i < 4; i++)
#pragma unroll
        for (int j = 0; j < 4; j++)
#pragma unroll
            for (int r = 0; r < 4; r++) acc[i][j][r] = 0.f;

#pragma unroll
    for (int m = 0; m < 4; m++)
#pragma unroll
        for (int h = 0; h < 2; h++) {
            int r = ld_r + h * 64;
            uint32_t sa = sb + 0 * STAGE_SB + m * TILE_SB + r * (SROW * 2) + ld_seg * 16;
            cp_async16(sa, gsrc[m] + (size_t)r * H_ + 0 * BK + ld_seg * 8);
        }
    cp_commit();

    for (int s = 0; s < 8; s++) {
        if (s + 1 < 8) {
            int buf = (s + 1) & 1;
#pragma unroll
            for (int m = 0; m < 4; m++)
#pragma unroll
                for (int h = 0; h < 2; h++) {
                    int r = ld_r + h * 64;
                    uint32_t sa = sb + buf * STAGE_SB + m * TILE_SB +
                                  r * (SROW * 2) + ld_seg * 16;
                    cp_async16(sa, gsrc[m] + (size_t)r * H_ + (s + 1) * BK + ld_seg * 8);
                }
            cp_commit();
            cp_wait<1>();
        } else {
            cp_wait<0>();
        }
        __syncthreads();

        const uint32_t base = sb + (s & 1) * STAGE_SB;
        const uint32_t sAhi = base;
        const uint32_t sAlo = base + TILE_SB;
        const uint32_t sBhi = base + 2 * TILE_SB;
        const uint32_t sBlo = base + 3 * TILE_SB;

#pragma unroll
        for (int kk = 0; kk < 2; kk++) {
            uint32_t ahi[4][4], alo[4][4], bhi[4][2], blo[4][2];
            const int a_row_l = (lane & 15);
            const int a_col   = kk * 16 + (lane >> 4) * 8;
#pragma unroll
            for (int mt = 0; mt < 4; mt++) {
                int r = wm * 64 + mt * 16 + a_row_l;
                uint32_t off = (uint32_t)(r * (SROW * 2) + a_col * 2);
                ldsm_x4(ahi[mt][0], ahi[mt][1], ahi[mt][2], ahi[mt][3], sAhi + off);
                ldsm_x4(alo[mt][0], alo[mt][1], alo[mt][2], alo[mt][3], sAlo + off);
            }
            const int b_row_l = (lane & 7);
            const int b_col   = kk * 16 + ((lane >> 3) & 1) * 8;
#pragma unroll
            for (int nt = 0; nt < 4; nt++) {
                int r = wn * 32 + nt * 8 + b_row_l;
                uint32_t off = (uint32_t)(r * (SROW * 2) + b_col * 2);
                ldsm_x2(bhi[nt][0], bhi[nt][1], sBhi + off);
                ldsm_x2(blo[nt][0], blo[nt][1], sBlo + off);
            }
#pragma unroll
            for (int mt = 0; mt < 4; mt++)
#pragma unroll
                for (int nt = 0; nt < 4; nt++) {
                    mma_bf16(acc[mt][nt], ahi[mt], bhi[nt]);
                    mma_bf16(acc[mt][nt], ahi[mt], blo[nt]);
                    mma_bf16(acc[mt][nt], alo[mt], bhi[nt]);
                }
        }
        __syncthreads();
    }

    const int er = lane >> 2;
    const int ec = (lane & 3) * 2;
#pragma unroll
    for (int mt = 0; mt < 4; mt++) {
#pragma unroll
        for (int nt = 0; nt < 4; nt++) {
            int col = col0 + wn * 32 + nt * 8 + ec;
            float bx = b_y[col], by = b_y[col + 1];
            int r0 = row0 + wm * 64 + mt * 16 + er;
            float2 v0 = make_float2(acc[mt][nt][0] + bx, acc[mt][nt][1] + by);
            float2 v1 = make_float2(acc[mt][nt][2] + bx, acc[mt][nt][3] + by);
            *reinterpret_cast<float2*>(out + (size_t)r0 * V_ + col) = v0;
            *reinterpret_cast<float2*>(out + (size_t)(r0 + 8) * V_ + col) = v1;
        }
    }
}

// ---------------- launch ----------------
extern "C" void kernel_launch(void* const* d_in, const int* in_sizes, int n_in,
                              void* d_out, int out_size)
{
    const int*   x_ind = (const int*)  d_in[0];
    const float* embed = (const float*)d_in[1];
    const float* U_i   = (const float*)d_in[2];
    const float* U_f   = (const float*)d_in[3];
    const float* U_g   = (const float*)d_in[4];
    const float* U_o   = (const float*)d_in[5];
    const float* W_i   = (const float*)d_in[6];
    const float* W_f   = (const float*)d_in[7];
    const float* W_g   = (const float*)d_in[8];
    const float* W_o   = (const float*)d_in[9];
    const float* b_i   = (const float*)d_in[10];
    const float* b_f   = (const float*)d_in[11];
    const float* b_g   = (const float*)d_in[12];
    const float* b_o   = (const float*)d_in[13];
    const float* W_hy  = (const float*)d_in[14];
    const float* b_y   = (const float*)d_in[15];
    float* out = (float*)d_out;

    cudaFuncSetAttribute(gemm2_kernel,
                         cudaFuncAttributeMaxDynamicSharedMemorySize, GEMM2_SMEM);
    cudaFuncSetAttribute(lstm_scan_cluster,
                         cudaFuncAttributeMaxDynamicSharedMemorySize, SCAN_SMEM_BYTES);

    // 1. pack concatenated gate weights
    {
        int total = E_ * G_;
        pack_kernel<<<(total + 255) / 256, 256>>>(U_i, U_f, U_g, U_o,
                                                  W_i, W_f, W_g, W_o,
                                                  b_i, b_f, b_g, b_o);
    }

    // 2. transpose + split W_hy for the tensor-core logits GEMM
    {
        dim3 grid(V_ / 32, H_ / 32);
        dim3 blk(32, 8);
        convW_kernel<<<grid, blk>>>(W_hy);
    }

    // 3. xproj[T][B][4H] = embed[x_ind] @ Ucat + bcat
    {
        dim3 grid(G_ / 128, (T_ * B_) / 128);
        sgemm_xproj<<<grid, 256>>>(embed, x_ind);
    }

    // 4. LSTM recurrence: 16 clusters x 8 CTAs, weights smem-resident
    lstm_scan_cluster<<<(B_ / NB) * CL_C, 128, SCAN_SMEM_BYTES>>>();

    // 5. logits[B][T][V] = hs @ W_hy + b_y  (mma.sync bf16, 3-term split)
    {
        dim3 grid(V_ / 128, (B_ * T_) / 128);
        gemm2_kernel<<<grid, 256, GEMM2_SMEM>>>(out, b_y);
    }
}